// round 2
// baseline (speedup 1.0000x reference)
#include <cuda_runtime.h>
#include <math.h>

#define T_  1024
#define H_  1024
#define I_  1024
#define E_  16
#define K_  8
#define TK_ (T_ * K_)

#define TM 128
#define TN 64
#define BK 16

// Scratch (allocations forbidden -> __device__ globals)
__device__ int   g_off[E_ + 1];
__device__ int   g_ptok[TK_];           // pair -> token
__device__ int   g_pos[TK_];            // (t*K + k) -> pair position
__device__ float g_act[(size_t)TK_ * I_];   // 32 MB
__device__ float g_down[(size_t)TK_ * H_];  // 32 MB

// ---------------------------------------------------------------------------
// Deterministic routing: bucket the 8192 (token,k) pairs by expert.
// Auto-detect index dtype: int32 (stride 1) vs int64 (stride 2, little-endian,
// values < 16 so odd 32-bit words are all zero).
// ---------------------------------------------------------------------------
__global__ void route_kernel(const int* __restrict__ idx32) {
    __shared__ int s_cnt[E_];
    __shared__ int s_off[E_ + 1];
    __shared__ int s_stride;
    int e = threadIdx.x;

    if (e == 0) {
        int odd_nonzero = 0;
        #pragma unroll 1
        for (int j = 1; j < 256; j += 2) odd_nonzero |= (idx32[j] != 0);
        s_stride = odd_nonzero ? 1 : 2;
    }
    __syncthreads();
    int stride = s_stride;

    if (e < E_) {
        int c = 0;
        for (int j = 0; j < TK_; j++) c += (idx32[j * stride] == e);
        s_cnt[e] = c;
    }
    __syncthreads();
    if (e == 0) {
        int a = 0;
        for (int i = 0; i < E_; i++) { s_off[i] = a; a += s_cnt[i]; }
        s_off[E_] = a;
        for (int i = 0; i <= E_; i++) g_off[i] = s_off[i];
    }
    __syncthreads();
    if (e < E_) {
        int p = s_off[e];
        for (int j = 0; j < TK_; j++) {
            if (idx32[j * stride] == e) {
                g_ptok[p] = j >> 3;   // token = j / K
                g_pos[j]  = p;
                p++;
            }
        }
    }
}

__device__ __forceinline__ float silu_f(float x) {
    return x / (1.0f + expf(-x));
}

// ---------------------------------------------------------------------------
// GEMM1: act[p, i] = silu(x[tok(p)] . Wg[e][i]) * (x[tok(p)] . Wu[e][i])
// Tile: TM=128 pairs x TN=64 i-cols, BK=16. 256 threads, 8x4 microtile,
// dual accumulators (gate & up), fused SiLU epilogue.
// ---------------------------------------------------------------------------
__global__ void __launch_bounds__(256, 2)
gemm1_kernel(const float* __restrict__ hidden, const float* __restrict__ gup) {
    int e    = blockIdx.z;
    int rbeg = g_off[e], rend = g_off[e + 1];
    int row0 = rbeg + blockIdx.y * TM;
    if (row0 >= rend) return;
    int i0 = blockIdx.x * TN;

    const float* Wg = gup + (size_t)e * (2 * I_) * H_ + (size_t)i0 * H_;
    const float* Wu = Wg + (size_t)I_ * H_;

    __shared__ float xs[BK][TM];
    __shared__ float gs[BK][TN];
    __shared__ float us[BK][TN];

    int tid = threadIdx.x;
    int r   = tid & (TM - 1);
    int c4  = tid >> 7;            // 0 or 1
    int wr  = tid & (TN - 1);
    int wc  = tid >> 6;            // 0..3
    int tx  = tid & 15;            // cols 4*tx..
    int ty  = tid >> 4;            // rows 8*ty..

    int pr  = row0 + r;
    int prc = (pr < rend) ? pr : (rend - 1);
    const float* xrow = hidden + (size_t)g_ptok[prc] * H_;
    const float* grow = Wg + (size_t)wr * H_;
    const float* urow = Wu + (size_t)wr * H_;

    float accg[8][4], accu[8][4];
    #pragma unroll
    for (int a = 0; a < 8; a++)
        #pragma unroll
        for (int b = 0; b < 4; b++) { accg[a][b] = 0.f; accu[a][b] = 0.f; }

    for (int k0 = 0; k0 < H_; k0 += BK) {
        float4 xv0 = *(const float4*)(xrow + k0 + 4 * c4);
        float4 xv1 = *(const float4*)(xrow + k0 + 4 * (c4 + 2));
        float4 gv  = *(const float4*)(grow + k0 + 4 * wc);
        float4 uv  = *(const float4*)(urow + k0 + 4 * wc);
        __syncthreads();
        xs[4 * c4 + 0][r] = xv0.x;  xs[4 * c4 + 1][r] = xv0.y;
        xs[4 * c4 + 2][r] = xv0.z;  xs[4 * c4 + 3][r] = xv0.w;
        xs[4 * (c4 + 2) + 0][r] = xv1.x;  xs[4 * (c4 + 2) + 1][r] = xv1.y;
        xs[4 * (c4 + 2) + 2][r] = xv1.z;  xs[4 * (c4 + 2) + 3][r] = xv1.w;
        gs[4 * wc + 0][wr] = gv.x;  gs[4 * wc + 1][wr] = gv.y;
        gs[4 * wc + 2][wr] = gv.z;  gs[4 * wc + 3][wr] = gv.w;
        us[4 * wc + 0][wr] = uv.x;  us[4 * wc + 1][wr] = uv.y;
        us[4 * wc + 2][wr] = uv.z;  us[4 * wc + 3][wr] = uv.w;
        __syncthreads();

        #pragma unroll
        for (int k = 0; k < BK; k++) {
            float4 a0 = *(const float4*)&xs[k][8 * ty];
            float4 a1 = *(const float4*)&xs[k][8 * ty + 4];
            float4 bg = *(const float4*)&gs[k][4 * tx];
            float4 bu = *(const float4*)&us[k][4 * tx];
            float av[8]  = {a0.x, a0.y, a0.z, a0.w, a1.x, a1.y, a1.z, a1.w};
            float bgv[4] = {bg.x, bg.y, bg.z, bg.w};
            float buv[4] = {bu.x, bu.y, bu.z, bu.w};
            #pragma unroll
            for (int rr = 0; rr < 8; rr++)
                #pragma unroll
                for (int cc = 0; cc < 4; cc++) {
                    accg[rr][cc] += av[rr] * bgv[cc];
                    accu[rr][cc] += av[rr] * buv[cc];
                }
        }
    }

    #pragma unroll
    for (int rr = 0; rr < 8; rr++) {
        int p = row0 + 8 * ty + rr;
        if (p < rend) {
            float4 o;
            o.x = silu_f(accg[rr][0]) * accu[rr][0];
            o.y = silu_f(accg[rr][1]) * accu[rr][1];
            o.z = silu_f(accg[rr][2]) * accu[rr][2];
            o.w = silu_f(accg[rr][3]) * accu[rr][3];
            *(float4*)&g_act[(size_t)p * I_ + i0 + 4 * tx] = o;
        }
    }
}

// ---------------------------------------------------------------------------
// GEMM2: down[p, h] = act[p] . Wd[e][h]   (unweighted; combine applies weights)
// ---------------------------------------------------------------------------
__global__ void __launch_bounds__(256, 2)
gemm2_kernel(const float* __restrict__ dproj) {
    int e    = blockIdx.z;
    int rbeg = g_off[e], rend = g_off[e + 1];
    int row0 = rbeg + blockIdx.y * TM;
    if (row0 >= rend) return;
    int h0 = blockIdx.x * TN;

    const float* Wd = dproj + (size_t)e * H_ * I_ + (size_t)h0 * I_;

    __shared__ float xs[BK][TM];
    __shared__ float bs[BK][TN];

    int tid = threadIdx.x;
    int r   = tid & (TM - 1);
    int c4  = tid >> 7;
    int wr  = tid & (TN - 1);
    int wc  = tid >> 6;
    int tx  = tid & 15;
    int ty  = tid >> 4;

    int pr  = row0 + r;
    int prc = (pr < rend) ? pr : (rend - 1);
    const float* arow = g_act + (size_t)prc * I_;
    const float* brow = Wd + (size_t)wr * I_;

    float acc[8][4];
    #pragma unroll
    for (int a = 0; a < 8; a++)
        #pragma unroll
        for (int b = 0; b < 4; b++) acc[a][b] = 0.f;

    for (int k0 = 0; k0 < I_; k0 += BK) {
        float4 xv0 = *(const float4*)(arow + k0 + 4 * c4);
        float4 xv1 = *(const float4*)(arow + k0 + 4 * (c4 + 2));
        float4 bv  = *(const float4*)(brow + k0 + 4 * wc);
        __syncthreads();
        xs[4 * c4 + 0][r] = xv0.x;  xs[4 * c4 + 1][r] = xv0.y;
        xs[4 * c4 + 2][r] = xv0.z;  xs[4 * c4 + 3][r] = xv0.w;
        xs[4 * (c4 + 2) + 0][r] = xv1.x;  xs[4 * (c4 + 2) + 1][r] = xv1.y;
        xs[4 * (c4 + 2) + 2][r] = xv1.z;  xs[4 * (c4 + 2) + 3][r] = xv1.w;
        bs[4 * wc + 0][wr] = bv.x;  bs[4 * wc + 1][wr] = bv.y;
        bs[4 * wc + 2][wr] = bv.z;  bs[4 * wc + 3][wr] = bv.w;
        __syncthreads();

        #pragma unroll
        for (int k = 0; k < BK; k++) {
            float4 a0 = *(const float4*)&xs[k][8 * ty];
            float4 a1 = *(const float4*)&xs[k][8 * ty + 4];
            float4 b4 = *(const float4*)&bs[k][4 * tx];
            float av[8] = {a0.x, a0.y, a0.z, a0.w, a1.x, a1.y, a1.z, a1.w};
            float bv4[4] = {b4.x, b4.y, b4.z, b4.w};
            #pragma unroll
            for (int rr = 0; rr < 8; rr++)
                #pragma unroll
                for (int cc = 0; cc < 4; cc++)
                    acc[rr][cc] += av[rr] * bv4[cc];
        }
    }

    #pragma unroll
    for (int rr = 0; rr < 8; rr++) {
        int p = row0 + 8 * ty + rr;
        if (p < rend) {
            float4 o = {acc[rr][0], acc[rr][1], acc[rr][2], acc[rr][3]};
            *(float4*)&g_down[(size_t)p * H_ + h0 + 4 * tx] = o;
        }
    }
}

// ---------------------------------------------------------------------------
// Combine: out[t, h] = sum_k w[t,k] * g_down[pos[t,k], h]
// ---------------------------------------------------------------------------
__global__ void combine_kernel(const float* __restrict__ tw, float* __restrict__ out) {
    int t = blockIdx.x;
    __shared__ int   pos[K_];
    __shared__ float w[K_];
    if (threadIdx.x < K_) {
        pos[threadIdx.x] = g_pos[t * K_ + threadIdx.x];
        w[threadIdx.x]   = tw[t * K_ + threadIdx.x];
    }
    __syncthreads();
    int h = 4 * threadIdx.x;
    float4 acc = {0.f, 0.f, 0.f, 0.f};
    #pragma unroll
    for (int k = 0; k < K_; k++) {
        float4 v = *(const float4*)&g_down[(size_t)pos[k] * H_ + h];
        float wk = w[k];
        acc.x += wk * v.x; acc.y += wk * v.y;
        acc.z += wk * v.z; acc.w += wk * v.w;
    }
    *(float4*)&out[(size_t)t * H_ + h] = acc;
}

// ---------------------------------------------------------------------------
extern "C" void kernel_launch(void* const* d_in, const int* in_sizes, int n_in,
                              void* d_out, int out_size) {
    const float* hidden = (const float*)d_in[0];      // [T, H] f32
    const int*   tk_idx = (const int*)d_in[1];        // [T, K] i32 or i64 (auto)
    const float* tk_w   = (const float*)d_in[2];      // [T, K] f32
    const float* gup    = (const float*)d_in[3];      // [E, 2I, H] f32
    const float* dproj  = (const float*)d_in[4];      // [E, H, I] f32
    float*       out    = (float*)d_out;              // [T, H] f32

    route_kernel<<<1, 32>>>(tk_idx);

    dim3 grid1(I_ / TN, (TK_ + TM - 1) / TM, E_);
    gemm1_kernel<<<grid1, 256>>>(hidden, gup);

    dim3 grid2(H_ / TN, (TK_ + TM - 1) / TM, E_);
    gemm2_kernel<<<grid2, 256>>>(dproj);

    combine_kernel<<<T_, 256>>>(tk_w, out);
}

// round 4
// speedup vs baseline: 1.7527x; 1.7527x over previous
#include <cuda_runtime.h>
#include <cstdint>
#include <math.h>

#define T_  1024
#define H_  1024
#define I_  1024
#define E_  16
#define K_  8
#define TK_ (T_ * K_)

// ---------------- scratch (no allocs allowed) ----------------
__device__ int   g_off[E_ + 1];
__device__ int   g_ptok[TK_];
__device__ int   g_pos[TK_];
__device__ float g_gu[(size_t)TK_ * 2 * I_];  // 64 MB
__device__ float g_act[(size_t)TK_ * I_];     // 32 MB
__device__ float g_down[(size_t)TK_ * H_];    // 32 MB

__device__ __forceinline__ void split1(float f, uint32_t& h, uint32_t& l) {
    asm("cvt.rna.tf32.f32 %0, %1;" : "=r"(h) : "f"(f));
    float r = f - __uint_as_float(h);
    asm("cvt.rna.tf32.f32 %0, %1;" : "=r"(l) : "f"(r));
}
__device__ __forceinline__ float silu_f(float x) { return x / (1.0f + expf(-x)); }

__device__ __forceinline__ void mma_tf32(float* c, const uint32_t* a, const uint32_t* b) {
    asm volatile(
        "mma.sync.aligned.m16n8k8.row.col.f32.tf32.tf32.f32 "
        "{%0,%1,%2,%3}, {%4,%5,%6,%7}, {%8,%9}, {%0,%1,%2,%3};"
        : "+f"(c[0]), "+f"(c[1]), "+f"(c[2]), "+f"(c[3])
        : "r"(a[0]), "r"(a[1]), "r"(a[2]), "r"(a[3]), "r"(b[0]), "r"(b[1]));
}

// ---------------- routing: stable chunked histogram ----------------
__global__ void route_kernel(const int* __restrict__ idx) {
    __shared__ int cnt[1024];
    __shared__ int off[1025];
    __shared__ int s_stride;
    int tid = threadIdx.x;
    if (tid == 0) {
        int nz = 0;
        #pragma unroll 1
        for (int j = 1; j < 256; j += 2) nz |= (idx[j] != 0);
        s_stride = nz ? 1 : 2;   // int32 vs int64 payload
    }
    __syncthreads();
    int stride = s_stride;
    int e = tid >> 6, c = tid & 63;
    int j0 = c * 128, j1 = j0 + 128;
    int cn = 0;
    for (int j = j0; j < j1; j++) cn += (idx[j * stride] == e);
    cnt[tid] = cn;
    __syncthreads();
    if (tid == 0) {
        int a = 0;
        for (int i = 0; i < 1024; i++) { off[i] = a; a += cnt[i]; }
        off[1024] = a;
        for (int ee = 0; ee <= E_; ee++) g_off[ee] = off[ee * 64];
    }
    __syncthreads();
    int p = off[tid];
    for (int j = j0; j < j1; j++) {
        if (idx[j * stride] == e) { g_ptok[p] = j >> 3; g_pos[j] = p; p++; }
    }
}

// ---------------------------------------------------------------------------
// Grouped GEMM, 3xTF32 mma.sync. CTA tile 128(M pairs) x 128(N), BK=32.
// 4 warps (2x2), warp tile 64x64 (mt=4 x nt=8 of m16n8k8).
// GATHER=1: A row = hidden[g_ptok[p]]; GATHER=0: A row = g_act[p].
// D[p][n0+n] = sum_k A[p][k] * B[e][n0+n][k]
// ---------------------------------------------------------------------------
#define LDP 36              // padded row stride (floats) in smem planes
#define PLANE (128 * LDP)   // one plane (A or B, hi or lo)
#define GSMEM (4 * PLANE * 4)   // bytes

template <int GATHER>
__global__ void __launch_bounds__(128, 2)
gemm_tc(const float* __restrict__ A, const float* __restrict__ B,
        float* __restrict__ D, int ncols) {
    int e    = blockIdx.z;
    int rbeg = g_off[e], rend = g_off[e + 1];
    int row0 = rbeg + blockIdx.y * 128;
    if (row0 >= rend) return;
    int n0 = blockIdx.x * 128;

    extern __shared__ uint32_t smem[];
    uint32_t* Ah = smem;
    uint32_t* Al = Ah + PLANE;
    uint32_t* Bh = Al + PLANE;
    uint32_t* Bl = Bh + PLANE;

    const float* Bb = B + (size_t)e * ncols * 1024 + (size_t)n0 * 1024;

    int tid  = threadIdx.x;
    int wid  = tid >> 5;
    int lane = tid & 31;
    int gid  = lane >> 2;     // 0..7
    int tig  = lane & 3;      // 0..3
    int wm   = (wid >> 1) * 64;   // warp M offset
    int wn   = (wid & 1) * 64;    // warp N offset

    // Global->smem mapping: 8 float4 per thread per tile (128x32 floats).
    const float* aptr[8];
    const float* bptr[8];
    int soff[8];
    #pragma unroll
    for (int j = 0; j < 8; j++) {
        int u = tid + 128 * j;
        int r = u >> 3, c4 = u & 7;
        int p = row0 + r; if (p >= rend) p = rend - 1;
        if (GATHER) aptr[j] = A + (size_t)g_ptok[p] * 1024 + c4 * 4;
        else        aptr[j] = A + (size_t)p * 1024 + c4 * 4;
        bptr[j] = Bb + (size_t)r * 1024 + c4 * 4;
        soff[j] = r * LDP + c4 * 4;
    }

    float acc[4][8][4];
    #pragma unroll
    for (int mt = 0; mt < 4; mt++)
        #pragma unroll
        for (int nt = 0; nt < 8; nt++)
            #pragma unroll
            for (int q = 0; q < 4; q++) acc[mt][nt][q] = 0.f;

    for (int it = 0; it < 32; it++) {
        int k0 = it * 32;
        __syncthreads();   // previous compute done; smem reusable
        #pragma unroll
        for (int j = 0; j < 8; j++) {
            float4 v = *(const float4*)(aptr[j] + k0);
            uint32_t h0,h1,h2,h3,l0,l1,l2,l3;
            split1(v.x,h0,l0); split1(v.y,h1,l1); split1(v.z,h2,l2); split1(v.w,h3,l3);
            uint32_t* d = Ah + soff[j];
            d[0]=h0; d[1]=h1; d[2]=h2; d[3]=h3;
            d = Al + soff[j];
            d[0]=l0; d[1]=l1; d[2]=l2; d[3]=l3;
            float4 w = *(const float4*)(bptr[j] + k0);
            split1(w.x,h0,l0); split1(w.y,h1,l1); split1(w.z,h2,l2); split1(w.w,h3,l3);
            d = Bh + soff[j];
            d[0]=h0; d[1]=h1; d[2]=h2; d[3]=h3;
            d = Bl + soff[j];
            d[0]=l0; d[1]=l1; d[2]=l2; d[3]=l3;
        }
        __syncthreads();

        #pragma unroll
        for (int k8 = 0; k8 < 4; k8++) {
            int kc = k8 * 8;
            uint32_t ah[4][4], al[4][4];
            #pragma unroll
            for (int mt = 0; mt < 4; mt++) {
                int base = (wm + mt * 16 + gid) * LDP + kc;
                ah[mt][0] = Ah[base + tig];
                ah[mt][1] = Ah[base + 8 * LDP + tig];
                ah[mt][2] = Ah[base + tig + 4];
                ah[mt][3] = Ah[base + 8 * LDP + tig + 4];
                al[mt][0] = Al[base + tig];
                al[mt][1] = Al[base + 8 * LDP + tig];
                al[mt][2] = Al[base + tig + 4];
                al[mt][3] = Al[base + 8 * LDP + tig + 4];
            }
            #pragma unroll
            for (int nt = 0; nt < 8; nt++) {
                int nb = (wn + nt * 8 + gid) * LDP + kc;
                uint32_t bh[2], bl[2];
                bh[0] = Bh[nb + tig];  bh[1] = Bh[nb + tig + 4];
                bl[0] = Bl[nb + tig];  bl[1] = Bl[nb + tig + 4];
                #pragma unroll
                for (int mt = 0; mt < 4; mt++) {
                    mma_tf32(acc[mt][nt], ah[mt], bh);
                    mma_tf32(acc[mt][nt], ah[mt], bl);
                    mma_tf32(acc[mt][nt], al[mt], bh);
                }
            }
        }
    }

    // Epilogue: D rows = pairs, cols = n0 + ...
    #pragma unroll
    for (int mt = 0; mt < 4; mt++) {
        int r0 = row0 + wm + mt * 16 + gid;
        #pragma unroll
        for (int nt = 0; nt < 8; nt++) {
            int col = n0 + wn + nt * 8 + tig * 2;
            if (r0 < rend) {
                float2 o = {acc[mt][nt][0], acc[mt][nt][1]};
                *(float2*)&D[(size_t)r0 * ncols + col] = o;
            }
            if (r0 + 8 < rend) {
                float2 o = {acc[mt][nt][2], acc[mt][nt][3]};
                *(float2*)&D[(size_t)(r0 + 8) * ncols + col] = o;
            }
        }
    }
}

// ---------------- silu: act[p][i] = silu(gu[p][i]) * gu[p][I+i] ----------------
__global__ void act_kernel() {
    int p = blockIdx.x;
    int c = threadIdx.x * 4;
    const float* row = &g_gu[(size_t)p * (2 * I_)];
    float4 g = *(const float4*)(row + c);
    float4 u = *(const float4*)(row + I_ + c);
    float4 o;
    o.x = silu_f(g.x) * u.x; o.y = silu_f(g.y) * u.y;
    o.z = silu_f(g.z) * u.z; o.w = silu_f(g.w) * u.w;
    *(float4*)&g_act[(size_t)p * I_ + c] = o;
}

// ---------------- combine ----------------
__global__ void combine_kernel(const float* __restrict__ tw, float* __restrict__ out) {
    int t = blockIdx.x;
    __shared__ int   pos[K_];
    __shared__ float w[K_];
    if (threadIdx.x < K_) {
        pos[threadIdx.x] = g_pos[t * K_ + threadIdx.x];
        w[threadIdx.x]   = tw[t * K_ + threadIdx.x];
    }
    __syncthreads();
    int h = 4 * threadIdx.x;
    float4 acc = {0.f, 0.f, 0.f, 0.f};
    #pragma unroll
    for (int k = 0; k < K_; k++) {
        float4 v = *(const float4*)&g_down[(size_t)pos[k] * H_ + h];
        float wk = w[k];
        acc.x += wk * v.x; acc.y += wk * v.y;
        acc.z += wk * v.z; acc.w += wk * v.w;
    }
    *(float4*)&out[(size_t)t * H_ + h] = acc;
}

// ---------------- launch ----------------
extern "C" void kernel_launch(void* const* d_in, const int* in_sizes, int n_in,
                              void* d_out, int out_size) {
    const float* hidden = (const float*)d_in[0];
    const int*   tk_idx = (const int*)d_in[1];
    const float* tk_w   = (const float*)d_in[2];
    const float* gup    = (const float*)d_in[3];
    const float* dproj  = (const float*)d_in[4];
    float*       out    = (float*)d_out;

    float* gu_p;   cudaGetSymbolAddress((void**)&gu_p,   g_gu);
    float* act_p;  cudaGetSymbolAddress((void**)&act_p,  g_act);
    float* down_p; cudaGetSymbolAddress((void**)&down_p, g_down);

    cudaFuncSetAttribute(gemm_tc<1>, cudaFuncAttributeMaxDynamicSharedMemorySize, GSMEM);
    cudaFuncSetAttribute(gemm_tc<0>, cudaFuncAttributeMaxDynamicSharedMemorySize, GSMEM);

    route_kernel<<<1, 1024>>>(tk_idx);
    gemm_tc<1><<<dim3(2 * I_ / 128, TK_ / 128, E_), 128, GSMEM>>>(hidden, gup, gu_p, 2 * I_);
    act_kernel<<<TK_, 256>>>();
    gemm_tc<0><<<dim3(H_ / 128, TK_ / 128, E_), 128, GSMEM>>>(act_p, dproj, down_p, H_);
    combine_kernel<<<T_, 256>>>(tk_w, out);
}

// round 5
// speedup vs baseline: 2.5264x; 1.4414x over previous
#include <cuda_runtime.h>
#include <cuda_bf16.h>
#include <cstdint>
#include <math.h>

#define T_  1024
#define H_  1024
#define I_  1024
#define E_  16
#define K_  8
#define TK_ (T_ * K_)

// ---------------- scratch (no allocs allowed) ----------------
__device__ int   g_off[E_ + 1];
__device__ int   g_ptok[TK_];
__device__ int   g_pos[TK_];
__device__ float g_act[(size_t)TK_ * I_];     // 32 MB
__device__ float g_down[(size_t)TK_ * H_];    // 32 MB

// smem geometry: bf16x2-pair planes, 128 rows x 16 pairs, padded stride 20
#define LDP   20
#define PLANE (128 * LDP)        // u32 per plane
#define BUFU  (4 * PLANE)        // Ah, Am, Bh, Bm
#define GSMEM (2 * BUFU * 4)     // 81920 bytes (double buffer)

__device__ __forceinline__ float silu_f(float x) { return x / (1.0f + expf(-x)); }

__device__ __forceinline__ void mma_bf16(float* c, const uint32_t* a, const uint32_t* b) {
    asm volatile(
        "mma.sync.aligned.m16n8k16.row.col.f32.bf16.bf16.f32 "
        "{%0,%1,%2,%3}, {%4,%5,%6,%7}, {%8,%9}, {%0,%1,%2,%3};"
        : "+f"(c[0]), "+f"(c[1]), "+f"(c[2]), "+f"(c[3])
        : "r"(a[0]), "r"(a[1]), "r"(a[2]), "r"(a[3]), "r"(b[0]), "r"(b[1]));
}

__device__ __forceinline__ uint32_t b2u(__nv_bfloat162 v) {
    return *reinterpret_cast<uint32_t*>(&v);
}

// float4 -> 2 hi-pairs + 2 mid-pairs (bf16x2, low half = even k)
__device__ __forceinline__ void split_f4(float4 v, uint32_t& h0, uint32_t& h1,
                                         uint32_t& m0, uint32_t& m1) {
    __nv_bfloat162 a = __floats2bfloat162_rn(v.x, v.y);
    __nv_bfloat162 b = __floats2bfloat162_rn(v.z, v.w);
    float rx = v.x - __bfloat162float(a.x);
    float ry = v.y - __bfloat162float(a.y);
    float rz = v.z - __bfloat162float(b.x);
    float rw = v.w - __bfloat162float(b.y);
    __nv_bfloat162 c = __floats2bfloat162_rn(rx, ry);
    __nv_bfloat162 d = __floats2bfloat162_rn(rz, rw);
    h0 = b2u(a); h1 = b2u(b); m0 = b2u(c); m1 = b2u(d);
}

// ---------------- routing: stable chunked histogram ----------------
__global__ void route_kernel(const int* __restrict__ idx) {
    __shared__ int cnt[1024];
    __shared__ int off[1025];
    __shared__ int s_stride;
    int tid = threadIdx.x;
    if (tid == 0) {
        int nz = 0;
        #pragma unroll 1
        for (int j = 1; j < 256; j += 2) nz |= (idx[j] != 0);
        s_stride = nz ? 1 : 2;   // int32 vs int64 payload
    }
    __syncthreads();
    int stride = s_stride;
    int e = tid >> 6, c = tid & 63;
    int j0 = c * 128, j1 = j0 + 128;
    int cn = 0;
    for (int j = j0; j < j1; j++) cn += (idx[j * stride] == e);
    cnt[tid] = cn;
    __syncthreads();
    if (tid == 0) {
        int a = 0;
        for (int i = 0; i < 1024; i++) { off[i] = a; a += cnt[i]; }
        off[1024] = a;
        for (int ee = 0; ee <= E_; ee++) g_off[ee] = off[ee * 64];
    }
    __syncthreads();
    int p = off[tid];
    for (int j = j0; j < j1; j++) {
        if (idx[j * stride] == e) { g_ptok[p] = j >> 3; g_pos[j] = p; p++; }
    }
}

// ---------------------------------------------------------------------------
// Grouped GEMM, 3x bf16-split mma.sync m16n8k16. CTA tile 128(M)x128(N), BK=32.
// 256 threads, 8 warps (4x2), warp tile 32x64 (mt=2, nt=8).
// FUSE=1 (GEMM1): A gathered from hidden, B rows = 64 gate + 64 up of i-block,
//                 epilogue computes silu(gate)*up -> g_act.
// FUSE=0 (GEMM2): A = g_act rows, B = down_proj, epilogue -> g_down.
// ---------------------------------------------------------------------------
template <int FUSE>
__global__ void __launch_bounds__(256, 1)
gemm_bf16(const float* __restrict__ A, const float* __restrict__ B,
          float* __restrict__ D) {
    int e    = blockIdx.z;
    int rbeg = g_off[e], rend = g_off[e + 1];
    int row0 = rbeg + blockIdx.y * 128;
    if (row0 >= rend) return;
    int n0 = blockIdx.x * (FUSE ? 64 : 128);   // i-block (FUSE) or h-block

    extern __shared__ uint32_t smem[];

    int tid  = threadIdx.x;
    int wid  = tid >> 5;
    int lane = tid & 31;
    int gid  = lane >> 2;
    int tig  = lane & 3;
    int wm   = (wid >> 1) * 32;   // 0,32,64,96
    int wn   = (wid & 1) * 64;    // 0,64

    // Global load mapping: 4 float4 per thread per matrix per K-tile (128x32 f32).
    const float* aptr[4];
    const float* bptr[4];
    int soff[4];
    #pragma unroll
    for (int j = 0; j < 4; j++) {
        int u = tid + 256 * j;
        int r = u >> 3, c4 = u & 7;
        int p = row0 + r; if (p >= rend) p = rend - 1;
        if (FUSE) aptr[j] = A + (size_t)g_ptok[p] * 1024 + c4 * 4;
        else      aptr[j] = A + (size_t)p * 1024 + c4 * 4;
        int br;
        if (FUSE) br = (r < 64) ? (n0 + r) : (I_ + n0 + r - 64);
        else      br = n0 + r;
        bptr[j] = B + ((size_t)e * (FUSE ? 2 * I_ : H_) + br) * 1024 + c4 * 4;
        soff[j] = r * LDP + c4 * 2;
    }

    float4 pa[4], pb[4];
    #pragma unroll
    for (int j = 0; j < 4; j++) { pa[j] = *(const float4*)aptr[j]; pb[j] = *(const float4*)bptr[j]; }

    // store tile 0 into buffer 0
    {
        uint32_t* Ah = smem;            uint32_t* Am = smem + PLANE;
        uint32_t* Bh = smem + 2*PLANE;  uint32_t* Bm = smem + 3*PLANE;
        #pragma unroll
        for (int j = 0; j < 4; j++) {
            uint32_t h0,h1,m0,m1;
            split_f4(pa[j], h0,h1,m0,m1);
            Ah[soff[j]] = h0; Ah[soff[j]+1] = h1; Am[soff[j]] = m0; Am[soff[j]+1] = m1;
            split_f4(pb[j], h0,h1,m0,m1);
            Bh[soff[j]] = h0; Bh[soff[j]+1] = h1; Bm[soff[j]] = m0; Bm[soff[j]+1] = m1;
        }
    }
    __syncthreads();

    float acc[2][8][4];
    #pragma unroll
    for (int mt = 0; mt < 2; mt++)
        #pragma unroll
        for (int nt = 0; nt < 8; nt++)
            #pragma unroll
            for (int q = 0; q < 4; q++) acc[mt][nt][q] = 0.f;

    for (int it = 0; it < 32; it++) {
        uint32_t* base = smem + (it & 1) * BUFU;
        uint32_t* Ah = base;            uint32_t* Am = base + PLANE;
        uint32_t* Bh = base + 2*PLANE;  uint32_t* Bm = base + 3*PLANE;

        // prefetch next K-tile into registers (latency hidden under MMAs)
        if (it < 31) {
            int k0 = (it + 1) * 32;
            #pragma unroll
            for (int j = 0; j < 4; j++) {
                pa[j] = *(const float4*)(aptr[j] + k0);
                pb[j] = *(const float4*)(bptr[j] + k0);
            }
        }

        #pragma unroll
        for (int kk = 0; kk < 2; kk++) {
            int po = kk * 8;  // pair offset within 16-pair row
            uint32_t ah[2][4], am[2][4];
            #pragma unroll
            for (int mt = 0; mt < 2; mt++) {
                int r = wm + mt * 16 + gid;
                int b0 = r * LDP + po + tig;
                int b1 = (r + 8) * LDP + po + tig;
                ah[mt][0] = Ah[b0];     ah[mt][1] = Ah[b1];
                ah[mt][2] = Ah[b0 + 4]; ah[mt][3] = Ah[b1 + 4];
                am[mt][0] = Am[b0];     am[mt][1] = Am[b1];
                am[mt][2] = Am[b0 + 4]; am[mt][3] = Am[b1 + 4];
            }
            uint32_t bh[8][2], bm[8][2];
            #pragma unroll
            for (int nt = 0; nt < 8; nt++) {
                int n = wn + nt * 8 + gid;
                int nb = n * LDP + po + tig;
                bh[nt][0] = Bh[nb]; bh[nt][1] = Bh[nb + 4];
                bm[nt][0] = Bm[nb]; bm[nt][1] = Bm[nb + 4];
            }
            #pragma unroll
            for (int nt = 0; nt < 8; nt++)
                #pragma unroll
                for (int mt = 0; mt < 2; mt++) {
                    mma_bf16(acc[mt][nt], ah[mt], bh[nt]);
                    mma_bf16(acc[mt][nt], ah[mt], bm[nt]);
                    mma_bf16(acc[mt][nt], am[mt], bh[nt]);
                }
        }

        // store prefetched tile into the other buffer
        if (it < 31) {
            uint32_t* nb = smem + ((it + 1) & 1) * BUFU;
            uint32_t* nAh = nb;            uint32_t* nAm = nb + PLANE;
            uint32_t* nBh = nb + 2*PLANE;  uint32_t* nBm = nb + 3*PLANE;
            #pragma unroll
            for (int j = 0; j < 4; j++) {
                uint32_t h0,h1,m0,m1;
                split_f4(pa[j], h0,h1,m0,m1);
                nAh[soff[j]] = h0; nAh[soff[j]+1] = h1; nAm[soff[j]] = m0; nAm[soff[j]+1] = m1;
                split_f4(pb[j], h0,h1,m0,m1);
                nBh[soff[j]] = h0; nBh[soff[j]+1] = h1; nBm[soff[j]] = m0; nBm[soff[j]+1] = m1;
            }
        }
        __syncthreads();
    }

    if (FUSE) {
        // recombine gate (cols 0..63) with up (cols 64..127) through smem
        float* s = (float*)smem;   // stride 132 floats, 128x128 tile (67.6 KB)
        #pragma unroll
        for (int mt = 0; mt < 2; mt++) {
            int r = wm + mt * 16 + gid;
            #pragma unroll
            for (int nt = 0; nt < 8; nt++) {
                int c = wn + nt * 8 + 2 * tig;
                s[r * 132 + c]       = acc[mt][nt][0];
                s[r * 132 + c + 1]   = acc[mt][nt][1];
                s[(r+8) * 132 + c]   = acc[mt][nt][2];
                s[(r+8) * 132 + c+1] = acc[mt][nt][3];
            }
        }
        __syncthreads();
        #pragma unroll
        for (int j = 0; j < 8; j++) {
            int u = tid + 256 * j;
            int r = u >> 4, cf = u & 15;
            int c = cf * 4;
            int p = row0 + r;
            if (p < rend) {
                float4 g = *(const float4*)&s[r * 132 + c];
                float4 up = *(const float4*)&s[r * 132 + 64 + c];
                float4 o;
                o.x = silu_f(g.x) * up.x; o.y = silu_f(g.y) * up.y;
                o.z = silu_f(g.z) * up.z; o.w = silu_f(g.w) * up.w;
                *(float4*)&D[(size_t)p * I_ + n0 + c] = o;
            }
        }
    } else {
        #pragma unroll
        for (int mt = 0; mt < 2; mt++) {
            int r0 = row0 + wm + mt * 16 + gid;
            #pragma unroll
            for (int nt = 0; nt < 8; nt++) {
                int col = n0 + wn + nt * 8 + 2 * tig;
                if (r0 < rend) {
                    float2 o = {acc[mt][nt][0], acc[mt][nt][1]};
                    *(float2*)&D[(size_t)r0 * H_ + col] = o;
                }
                if (r0 + 8 < rend) {
                    float2 o = {acc[mt][nt][2], acc[mt][nt][3]};
                    *(float2*)&D[(size_t)(r0 + 8) * H_ + col] = o;
                }
            }
        }
    }
}

// ---------------- combine ----------------
__global__ void combine_kernel(const float* __restrict__ tw, float* __restrict__ out) {
    int t = blockIdx.x;
    __shared__ int   pos[K_];
    __shared__ float w[K_];
    if (threadIdx.x < K_) {
        pos[threadIdx.x] = g_pos[t * K_ + threadIdx.x];
        w[threadIdx.x]   = tw[t * K_ + threadIdx.x];
    }
    __syncthreads();
    int h = 4 * threadIdx.x;
    float4 acc = {0.f, 0.f, 0.f, 0.f};
    #pragma unroll
    for (int k = 0; k < K_; k++) {
        float4 v = *(const float4*)&g_down[(size_t)pos[k] * H_ + h];
        float wk = w[k];
        acc.x += wk * v.x; acc.y += wk * v.y;
        acc.z += wk * v.z; acc.w += wk * v.w;
    }
    *(float4*)&out[(size_t)t * H_ + h] = acc;
}

// ---------------- launch ----------------
extern "C" void kernel_launch(void* const* d_in, const int* in_sizes, int n_in,
                              void* d_out, int out_size) {
    const float* hidden = (const float*)d_in[0];
    const int*   tk_idx = (const int*)d_in[1];
    const float* tk_w   = (const float*)d_in[2];
    const float* gup    = (const float*)d_in[3];
    const float* dproj  = (const float*)d_in[4];
    float*       out    = (float*)d_out;

    float* act_p;  cudaGetSymbolAddress((void**)&act_p,  g_act);
    float* down_p; cudaGetSymbolAddress((void**)&down_p, g_down);

    cudaFuncSetAttribute(gemm_bf16<1>, cudaFuncAttributeMaxDynamicSharedMemorySize, GSMEM);
    cudaFuncSetAttribute(gemm_bf16<0>, cudaFuncAttributeMaxDynamicSharedMemorySize, GSMEM);

    route_kernel<<<1, 1024>>>(tk_idx);
    gemm_bf16<1><<<dim3(I_ / 64, TK_ / 128, E_), 256, GSMEM>>>(hidden, gup, act_p);
    gemm_bf16<0><<<dim3(H_ / 128, TK_ / 128, E_), 256, GSMEM>>>(act_p, dproj, down_p);
    combine_kernel<<<T_, 256>>>(tk_w, out);
}